// round 10
// baseline (speedup 1.0000x reference)
#include <cuda_runtime.h>
#include <math.h>

// Problem constants (fixed by the reference)
#define T  1024
#define B  256
#define H  20
#define FULL 0xffffffffu
#define OSTRIDE (B * 3)          // 768 floats between consecutive time rows

// Memory kernel me[t] = sigmoid(MLP(t))
__device__ float g_me[T];

// ---------------------------------------------------------------------------
// Kernel 1: tiny MLP over the T time points. One thread per time point.
// ---------------------------------------------------------------------------
__global__ void mlp_kernel(const float* __restrict__ t,
                           const float* __restrict__ w1, const float* __restrict__ b1,
                           const float* __restrict__ w2, const float* __restrict__ b2,
                           const float* __restrict__ w3, const float* __restrict__ b3,
                           const float* __restrict__ w4, const float* __restrict__ b4)
{
    int i = blockIdx.x * blockDim.x + threadIdx.x;
    if (i >= T) return;
    float x = t[i];

    float h1[H], h2[H], h3[H];
#pragma unroll
    for (int j = 0; j < H; ++j) h1[j] = tanhf(x * w1[j] + b1[j]);

#pragma unroll
    for (int j = 0; j < H; ++j) {
        float s = b2[j];
#pragma unroll
        for (int k = 0; k < H; ++k) s += h1[k] * w2[k * H + j];
        h2[j] = tanhf(s);
    }

#pragma unroll
    for (int j = 0; j < H; ++j) {
        float s = b3[j];
#pragma unroll
        for (int k = 0; k < H; ++k) s += h2[k] * w3[k * H + j];
        h3[j] = tanhf(s);
    }

    float s = b4[0];
#pragma unroll
    for (int k = 0; k < H; ++k) s += h3[k] * w4[k];

    g_me[i] = 1.0f / (1.0f + expf(-s));   // sigmoid
}

// ---------------------------------------------------------------------------
// Kernel 2: TWO batch elements per block, 128 blocks (one wave).
//   warp 0    : DUAL near chain — both batches' sequential chains interleaved
//               in one instruction stream (fills the 4-cyc FMA dependency
//               gaps that left the near SMSP at ~0.25 IPC).
//   warps 1-3 : far helpers for batch A;  warps 4-6: far helpers for batch B.
// Near chain: 32-step chunks, 4-step lookahead broadcast (shfl result first
// consumed 4 steps after issue; last 4 near taps accumulated redundantly).
// Cross-chunk taps are read from smem per chunk (no tapR register array).
// ---------------------------------------------------------------------------
__global__ void __launch_bounds__(224, 1)
solver_kernel(const float* __restrict__ t,
              const float* __restrict__ y,
              const float* __restrict__ beta_p,
              const float* __restrict__ gamma_p,
              float* __restrict__ out)
{
    __shared__ __align__(16) float rkp[32 + T];     // rk[m]=me[T-1-m]; rkp[0..31]=0 pad
    __shared__ __align__(16) float ihp[2][32 + T];  // per-batch I history (+32 zero pad)
    __shared__ float farbuf[2][2][3][32];           // [half][parity][hw][lane]

    const int tid  = threadIdx.x;
    const int w    = tid >> 5;
    const int lane = tid & 31;

    // Cooperative init
    for (int i = tid; i < 32 + T; i += 224) rkp[i] = (i < 32) ? 0.0f : g_me[T - 1 - (i - 32)];
    for (int i = tid; i < 2 * (32 + T); i += 224) (&ihp[0][0])[i] = 0.0f;
    for (int i = tid; i < 384; i += 224) (&farbuf[0][0][0][0])[i] = 0.0f;

    const float dt    = t[0] - t[1];       // = 1/(T-1), positive
    const float beta  = beta_p[0];
    const float gamma = gamma_p[0];

    const int bA = blockIdx.x * 2;
    const int bB = bA + 1;
    float* ihA = ihp[0] + 32;
    float* ihB = ihp[1] + 32;

    // Both states loaded by the near warp (harmless in helpers).
    float SA = y[bA * 3 + 0], IA = y[bA * 3 + 1], RA = y[bA * 3 + 2];
    float SB = y[bB * 3 + 0], IB = y[bB * 3 + 1], RB = y[bB * 3 + 2];

    if (w == 0) {
        if (lane == 0) ihA[0] = IA;
        if (lane == 4) ihB[0] = IB;
        // solution[0] = y0 ; diff[T-1] = 0 (d_out poisoned -> must be written)
        if (lane < 3) {
            float sv = (lane == 0) ? SA : ((lane == 1) ? IA : RA);
            out[bA * 3 + lane] = sv;
            out[(size_t)T * OSTRIDE + (T - 1) * OSTRIDE + bA * 3 + lane] = 0.0f;
        }
        if (lane >= 4 && lane < 7) {
            const int l3 = lane - 4;
            float sv = (l3 == 0) ? SB : ((l3 == 1) ? IB : RB);
            out[bB * 3 + l3] = sv;
            out[(size_t)T * OSTRIDE + (T - 1) * OSTRIDE + bB * 3 + l3] = 0.0f;
        }
    }
    __syncthreads();

    const float* rk = rkp + 32;

    // Near-warp register taps (uniform per lane, compile-time indexed).
    float tap[32];
#pragma unroll
    for (int s = 0; s < 32; ++s) tap[s] = rkp[32 + lane - s];    // rk[lane-s], pad=0
    const float rq0 = rk[0], rq1 = rk[1], rq2 = rk[2], rq3 = rk[3];

    float* psA0 = out + bA * 3 + lane;                        // solution rows (A)
    float* pdA0 = out + (size_t)T * OSTRIDE + bA * 3 + lane;  // diff rows (A)
    float* psB0 = out + bB * 3 + (lane & 3);                  // lanes 4-6 -> comps 0-2
    float* pdB0 = out + (size_t)T * OSTRIDE + bB * 3 + (lane & 3);

    const bool stA = (lane < 3);
    const bool stB = (lane >= 4 && lane < 7);

    // ---------------- main loop: chunks 0..30 (32 steps each) ---------------
    for (int c = 0; c < 31; ++c) {
        if (w == 0) {
            const int base = c << 5;
            float accA = farbuf[0][c & 1][0][lane] + farbuf[0][c & 1][1][lane]
                       + farbuf[0][c & 1][2][lane];
            float accB = farbuf[1][c & 1][0][lane] + farbuf[1][c & 1][1][lane]
                       + farbuf[1][c & 1][2][lane];
            // Cross terms from previous chunk (taps straight from smem).
#pragma unroll
            for (int u = 0; u < 32; ++u) {
                const float tr = rkp[64 + lane - u];          // rk[lane+32-u]
                accA = fmaf(tr, ihA[base - 32 + u], accA);    // pad zeros for c=0
                accB = fmaf(tr, ihB[base - 32 + u], accB);
            }

            // Lookahead rings (4-step)
            float aPA[4], nPA[4], aPB[4], nPB[4];
#pragma unroll
            for (int q = 0; q < 4; ++q) { nPA[q] = 0.0f; nPB[q] = 0.0f; }
            aPA[0] = __shfl_sync(FULL, accA, 0);
            aPA[1] = __shfl_sync(FULL, accA, 1);
            aPA[2] = __shfl_sync(FULL, accA, 2);
            aPA[3] = __shfl_sync(FULL, accA, 3);
            aPB[0] = __shfl_sync(FULL, accB, 0);
            aPB[1] = __shfl_sync(FULL, accB, 1);
            aPB[2] = __shfl_sync(FULL, accB, 2);
            aPB[3] = __shfl_sync(FULL, accB, 3);

            float* psA = psA0 + base * OSTRIDE;
            float* pdA = pdA0 + base * OSTRIDE;
            float* psB = psB0 + base * OSTRIDE;
            float* pdB = pdB0 + base * OSTRIDE;

#pragma unroll
            for (int s = 0; s < 32; ++s) {
                // ring near-updates (compile-time guards)
                if (s + 3 <= 31) { nPA[(s + 3) & 3] = rq3 * IA; nPB[(s + 3) & 3] = rq3 * IB; }
                if (s + 2 <= 31) { nPA[(s + 2) & 3] = fmaf(rq2, IA, nPA[(s + 2) & 3]);
                                   nPB[(s + 2) & 3] = fmaf(rq2, IB, nPB[(s + 2) & 3]); }
                if (s + 1 <= 31) { nPA[(s + 1) & 3] = fmaf(rq1, IA, nPA[(s + 1) & 3]);
                                   nPB[(s + 1) & 3] = fmaf(rq1, IB, nPB[(s + 1) & 3]); }
                nPA[s & 3] = fmaf(rq0, IA, nPA[s & 3]);
                nPB[s & 3] = fmaf(rq0, IB, nPB[s & 3]);

                const float integA = dt * (aPA[s & 3] + nPA[s & 3]);
                const float integB = dt * (aPB[s & 3] + nPB[s & 3]);

                accA = fmaf(tap[s], IA, accA);
                accB = fmaf(tap[s], IB, accB);
                if (s + 4 <= 31) {
                    aPA[(s + 4) & 3] = __shfl_sync(FULL, accA, s + 4);
                    aPB[(s + 4) & 3] = __shfl_sync(FULL, accB, s + 4);
                }

                const float bSIA = beta * SA * IA;
                const float gIA  = gamma * IA;
                const float dSA  = integA - bSIA;
                const float dIA  = bSIA - gIA;
                const float dRA  = gIA - integA;
                SA = fmaf(dSA, dt, SA);
                IA = fmaf(dIA, dt, IA);
                RA = fmaf(dRA, dt, RA);

                const float bSIB = beta * SB * IB;
                const float gIB  = gamma * IB;
                const float dSB  = integB - bSIB;
                const float dIB  = bSIB - gIB;
                const float dRB  = gIB - integB;
                SB = fmaf(dSB, dt, SB);
                IB = fmaf(dIB, dt, IB);
                RB = fmaf(dRB, dt, RB);

                const float svA = (lane == 0) ? SA  : ((lane == 1) ? IA  : RA);
                const float dvA = (lane == 0) ? dSA : ((lane == 1) ? dIA : dRA);
                const int   l3  = lane & 3;
                const float svB = (l3 == 0) ? SB  : ((l3 == 1) ? IB  : RB);
                const float dvB = (l3 == 0) ? dSB : ((l3 == 1) ? dIB : dRB);
                if (stA) { psA[(s + 1) * OSTRIDE] = svA; pdA[s * OSTRIDE] = dvA; }
                if (stB) { psB[(s + 1) * OSTRIDE] = svB; pdB[s * OSTRIDE] = dvB; }
                if (lane == 0) ihA[base + s + 1] = IA;
                if (lane == 4) ihB[base + s + 1] = IB;
            }
        } else {
            // Helpers: far for chunk c+1 over history t < 32c, 4x unrolled,
            // 16 independent accumulators (all indices compile-time).
            const int half = (w - 1) / 3;                   // 0=A, 1=B
            const int hw   = (w - 1) % 3;
            const float* ih = ihp[half] + 32;

            float hs[4][4];
#pragma unroll
            for (int u = 0; u < 4; ++u)
#pragma unroll
                for (int v = 0; v < 4; ++v) hs[u][v] = 0.0f;

            const float*  rf  = rk + ((c + 1) << 5) + lane; // rf[-t] = rk[32(c+1)+lane-t]
            const float4* ih4 = (const float4*)ih;
            const int n4 = (c << 5) >> 2;                   // 8c float4 groups
            int q = hw;
            for (; q + 9 < n4; q += 12) {
#pragma unroll
                for (int u = 0; u < 4; ++u) {
                    const int qq = q + 3 * u;
                    const float4 iv = ih4[qq];
                    const int tq = qq << 2;
                    hs[u][0] = fmaf(rf[-tq],       iv.x, hs[u][0]);
                    hs[u][1] = fmaf(rf[-(tq + 1)], iv.y, hs[u][1]);
                    hs[u][2] = fmaf(rf[-(tq + 2)], iv.z, hs[u][2]);
                    hs[u][3] = fmaf(rf[-(tq + 3)], iv.w, hs[u][3]);
                }
            }
            for (; q < n4; q += 3) {
                const float4 iv = ih4[q];
                const int tq = q << 2;
                hs[0][0] = fmaf(rf[-tq],       iv.x, hs[0][0]);
                hs[0][1] = fmaf(rf[-(tq + 1)], iv.y, hs[0][1]);
                hs[0][2] = fmaf(rf[-(tq + 2)], iv.z, hs[0][2]);
                hs[0][3] = fmaf(rf[-(tq + 3)], iv.w, hs[0][3]);
            }
            const float r0 = (hs[0][0] + hs[0][1]) + (hs[0][2] + hs[0][3]);
            const float r1 = (hs[1][0] + hs[1][1]) + (hs[1][2] + hs[1][3]);
            const float r2 = (hs[2][0] + hs[2][1]) + (hs[2][2] + hs[2][3]);
            const float r3 = (hs[3][0] + hs[3][1]) + (hs[3][2] + hs[3][3]);
            farbuf[half][(c + 1) & 1][hw][lane] = (r0 + r1) + (r2 + r3);
        }
        __syncthreads();   // farbuf handoff + ih visibility for next chunk
    }

    // ---------------- final chunk c=31: steps 992..1022 (31 steps) ----------
    if (w == 0) {
        const int base = 31 << 5;   // 992
        float accA = farbuf[0][1][0][lane] + farbuf[0][1][1][lane] + farbuf[0][1][2][lane];
        float accB = farbuf[1][1][0][lane] + farbuf[1][1][1][lane] + farbuf[1][1][2][lane];
#pragma unroll
        for (int u = 0; u < 32; ++u) {
            const float tr = rkp[64 + lane - u];
            accA = fmaf(tr, ihA[base - 32 + u], accA);
            accB = fmaf(tr, ihB[base - 32 + u], accB);
        }

        float aPA[4], nPA[4], aPB[4], nPB[4];
#pragma unroll
        for (int q = 0; q < 4; ++q) { nPA[q] = 0.0f; nPB[q] = 0.0f; }
        aPA[0] = __shfl_sync(FULL, accA, 0);
        aPA[1] = __shfl_sync(FULL, accA, 1);
        aPA[2] = __shfl_sync(FULL, accA, 2);
        aPA[3] = __shfl_sync(FULL, accA, 3);
        aPB[0] = __shfl_sync(FULL, accB, 0);
        aPB[1] = __shfl_sync(FULL, accB, 1);
        aPB[2] = __shfl_sync(FULL, accB, 2);
        aPB[3] = __shfl_sync(FULL, accB, 3);

        float* psA = psA0 + base * OSTRIDE;
        float* pdA = pdA0 + base * OSTRIDE;
        float* psB = psB0 + base * OSTRIDE;
        float* pdB = pdB0 + base * OSTRIDE;

#pragma unroll
        for (int s = 0; s < 31; ++s) {
            if (s + 3 <= 30) { nPA[(s + 3) & 3] = rq3 * IA; nPB[(s + 3) & 3] = rq3 * IB; }
            if (s + 2 <= 30) { nPA[(s + 2) & 3] = fmaf(rq2, IA, nPA[(s + 2) & 3]);
                               nPB[(s + 2) & 3] = fmaf(rq2, IB, nPB[(s + 2) & 3]); }
            if (s + 1 <= 30) { nPA[(s + 1) & 3] = fmaf(rq1, IA, nPA[(s + 1) & 3]);
                               nPB[(s + 1) & 3] = fmaf(rq1, IB, nPB[(s + 1) & 3]); }
            nPA[s & 3] = fmaf(rq0, IA, nPA[s & 3]);
            nPB[s & 3] = fmaf(rq0, IB, nPB[s & 3]);

            const float integA = dt * (aPA[s & 3] + nPA[s & 3]);
            const float integB = dt * (aPB[s & 3] + nPB[s & 3]);

            accA = fmaf(tap[s], IA, accA);
            accB = fmaf(tap[s], IB, accB);
            if (s + 4 <= 30) {
                aPA[(s + 4) & 3] = __shfl_sync(FULL, accA, s + 4);
                aPB[(s + 4) & 3] = __shfl_sync(FULL, accB, s + 4);
            }

            const float bSIA = beta * SA * IA;
            const float gIA  = gamma * IA;
            const float dSA  = integA - bSIA;
            const float dIA  = bSIA - gIA;
            const float dRA  = gIA - integA;
            SA = fmaf(dSA, dt, SA);
            IA = fmaf(dIA, dt, IA);
            RA = fmaf(dRA, dt, RA);

            const float bSIB = beta * SB * IB;
            const float gIB  = gamma * IB;
            const float dSB  = integB - bSIB;
            const float dIB  = bSIB - gIB;
            const float dRB  = gIB - integB;
            SB = fmaf(dSB, dt, SB);
            IB = fmaf(dIB, dt, IB);
            RB = fmaf(dRB, dt, RB);

            const float svA = (lane == 0) ? SA  : ((lane == 1) ? IA  : RA);
            const float dvA = (lane == 0) ? dSA : ((lane == 1) ? dIA : dRA);
            const int   l3  = lane & 3;
            const float svB = (l3 == 0) ? SB  : ((l3 == 1) ? IB  : RB);
            const float dvB = (l3 == 0) ? dSB : ((l3 == 1) ? dIB : dRB);
            if (stA) { psA[(s + 1) * OSTRIDE] = svA; pdA[s * OSTRIDE] = dvA; }
            if (stB) { psB[(s + 1) * OSTRIDE] = svB; pdB[s * OSTRIDE] = dvB; }
        }
    }
}

// ---------------------------------------------------------------------------
// Launch: two kernels, stream-ordered, graph-capturable, allocation-free.
// Input order (metadata): t, y, w1, b1, w2, b2, w3, b3, w4, b4, beta, gamma
// Output: [solution (T,B,3) | diff (T,B,3)] float32
// ---------------------------------------------------------------------------
extern "C" void kernel_launch(void* const* d_in, const int* in_sizes, int n_in,
                              void* d_out, int out_size)
{
    const float* t  = (const float*)d_in[0];
    const float* y  = (const float*)d_in[1];
    const float* w1 = (const float*)d_in[2];
    const float* b1 = (const float*)d_in[3];
    const float* w2 = (const float*)d_in[4];
    const float* b2 = (const float*)d_in[5];
    const float* w3 = (const float*)d_in[6];
    const float* b3 = (const float*)d_in[7];
    const float* w4 = (const float*)d_in[8];
    const float* b4 = (const float*)d_in[9];
    const float* be = (const float*)d_in[10];
    const float* ga = (const float*)d_in[11];
    float* out = (float*)d_out;

    mlp_kernel<<<4, 256>>>(t, w1, b1, w2, b2, w3, b3, w4, b4);
    solver_kernel<<<B / 2, 224>>>(t, y, be, ga, out);
}

// round 11
// speedup vs baseline: 2.1693x; 2.1693x over previous
#include <cuda_runtime.h>
#include <math.h>

// Problem constants (fixed by the reference)
#define T  1024
#define B  256
#define H  20
#define OSTRIDE (B * 3)          // 768 floats between consecutive time rows
#define IHP 1060                 // ih row pitch (words): 16B-aligned, %32==4

// Memory kernel me[t] = sigmoid(MLP(t))
__device__ float g_me[T];

// ---------------------------------------------------------------------------
// Kernel 1: tiny MLP over the T time points. One thread per time point.
// ---------------------------------------------------------------------------
__global__ void mlp_kernel(const float* __restrict__ t,
                           const float* __restrict__ w1, const float* __restrict__ b1,
                           const float* __restrict__ w2, const float* __restrict__ b2,
                           const float* __restrict__ w3, const float* __restrict__ b3,
                           const float* __restrict__ w4, const float* __restrict__ b4)
{
    int i = blockIdx.x * blockDim.x + threadIdx.x;
    if (i >= T) return;
    float x = t[i];

    float h1[H], h2[H], h3[H];
#pragma unroll
    for (int j = 0; j < H; ++j) h1[j] = tanhf(x * w1[j] + b1[j]);

#pragma unroll
    for (int j = 0; j < H; ++j) {
        float s = b2[j];
#pragma unroll
        for (int k = 0; k < H; ++k) s += h1[k] * w2[k * H + j];
        h2[j] = tanhf(s);
    }

#pragma unroll
    for (int j = 0; j < H; ++j) {
        float s = b3[j];
#pragma unroll
        for (int k = 0; k < H; ++k) s += h2[k] * w3[k * H + j];
        h3[j] = tanhf(s);
    }

    float s = b4[0];
#pragma unroll
    for (int k = 0; k < H; ++k) s += h3[k] * w4[k];

    g_me[i] = 1.0f / (1.0f + expf(-s));   // sigmoid
}

// ---------------------------------------------------------------------------
// Kernel 2: BATCH-PER-LANE. 2 batches per block, 128 blocks (one wave).
//   warp 0      : state warp. Lane owns one batch (lane&1 -> batch; lanes 2-31
//                 mirror). Near sum = registers only. ZERO cross-lane ops.
//   warps 1..4  : (h,half) = ((w-1)>>1,(w-1)&1): far dot for chunk c+1 over
//                 t < 32c, float4 data + float4 taps (4 shifted rk copies).
//                 half==0 warps also do per-chunk catch-up + fsum fold.
// Per chunk: [phaseA: catchup+fsum] bar [phaseB: near | far(c+1)] bar.
// integ(idx=32c+s) = dt*( fsum[s] (far t<32c-32 + catchup [32c-32,32c))
//                       + sum_{u<=s} rk[s-u]*Iv[u] ).
// ---------------------------------------------------------------------------
__global__ void __launch_bounds__(160, 1)
solver_kernel(const float* __restrict__ t,
              const float* __restrict__ y,
              const float* __restrict__ beta_p,
              const float* __restrict__ gamma_p,
              float* __restrict__ out)
{
    __shared__ __align__(16) float rkp[1056];        // rkp[32+l]=rk[l]; [0..31]=0
    __shared__ __align__(16) float rks4[4][1088];    // rks4[r][i] = rkp[i+r] (0-pad)
    __shared__ __align__(16) float ih[2][IHP];       // per-batch I history
    __shared__ float fbA[2][32][2], fbB[2][32][2];   // far partials [parity][s][b]
    __shared__ float fsum[32][2];                    // far+catchup, per chunk

    const int tid  = threadIdx.x;
    const int w    = tid >> 5;
    const int lane = tid & 31;

    // ---- cooperative init ----
    for (int i = tid; i < 1056; i += 160)
        rkp[i] = (i < 32) ? 0.0f : g_me[T - 1 - (i - 32)];
    for (int i = tid; i < 4 * 1088; i += 160) {
        const int r = i / 1088, j = i - r * 1088, k = j + r;
        (&rks4[0][0])[i] = (k >= 32 && k < 1056) ? g_me[T - 1 - (k - 32)] : 0.0f;
    }
    for (int i = tid; i < 2 * IHP; i += 160) (&ih[0][0])[i] = 0.0f;
    if (tid < 128) { (&fbA[0][0][0])[tid] = 0.0f; (&fbB[0][0][0])[tid] = 0.0f; }

    const float dt    = t[0] - t[1];       // = 1/(T-1), positive
    const float beta  = beta_p[0];
    const float gamma = gamma_p[0];

    const int h  = lane & 1;               // state warp: lane's batch slot
    const int bb = blockIdx.x * 2 + h;     // global batch id

    float S = y[bb * 3 + 0];
    float I = y[bb * 3 + 1];
    float R = y[bb * 3 + 2];

    float* ps_base = out + bb * 3;                        // solution rows
    float* pd_base = out + (size_t)T * OSTRIDE + bb * 3;  // diff rows

    if (w == 0 && lane < 2) {
        // solution[0] = y0 ; diff[T-1] = 0 (d_out poisoned -> must be written)
        ps_base[0] = S; ps_base[1] = I; ps_base[2] = R;
        float* pz = pd_base + (T - 1) * OSTRIDE;
        pz[0] = 0.0f; pz[1] = 0.0f; pz[2] = 0.0f;
    }
    __syncthreads();

    // State warp: scalar taps in registers (uniform across lanes).
    float tapc[32];
#pragma unroll
    for (int j = 0; j < 32; ++j) tapc[j] = rkp[32 + j];   // rk[j]

    const int fh   = (w >= 1) ? ((w - 1) >> 1) : 0;       // helper batch slot
    const int half = (w >= 1) ? ((w - 1) & 1) : 0;

    float Iv[32];

    // ------------------- chunks 0..30 (32 steps each) -----------------------
    for (int c = 0; c < 31; ++c) {
        const int base = c << 5;

        // phase A: catchup + fold into fsum (half==0 helper warps; lane = s)
        if (w >= 1 && half == 0) {
            float cu = 0.0f;
            if (c > 0) {
                const float* ihh = ih[fh] + base - 32;
#pragma unroll
                for (int j = 0; j < 32; ++j)
                    cu = fmaf(rkp[64 + lane - j], ihh[j], cu);   // rk[s+32-j]
            }
            fsum[lane][fh] = fbA[c & 1][lane][fh] + fbB[c & 1][lane][fh] + cu;
        }
        __syncthreads();

        // phase B
        if (w == 0) {
            // prefetch ring of fsum
            float fr[4];
            fr[0] = fsum[0][h]; fr[1] = fsum[1][h];
            fr[2] = fsum[2][h]; fr[3] = fsum[3][h];

#pragma unroll
            for (int s = 0; s < 32; ++s) {
                Iv[s] = I;
                float a0 = fr[s & 3], a1 = 0.0f;
#pragma unroll
                for (int u = 0; u <= s; ++u) {
                    if (u & 1) a1 = fmaf(tapc[s - u], Iv[u], a1);
                    else       a0 = fmaf(tapc[s - u], Iv[u], a0);
                }
                if (s + 4 < 32) fr[(s + 4) & 3] = fsum[s + 4][h];

                const float integ = dt * (a0 + a1);
                const float bSI = beta * S * I;
                const float gI  = gamma * I;
                const float dS  = integ - bSI;
                const float dI  = bSI - gI;
                const float dR  = gI - integ;
                S = fmaf(dS, dt, S);
                I = fmaf(dI, dt, I);
                R = fmaf(dR, dt, R);

                if (lane < 2) {
                    float* p1 = ps_base + (base + s + 1) * OSTRIDE;
                    float* p2 = pd_base + (base + s) * OSTRIDE;
                    p1[0] = S;  p1[1] = I;  p1[2] = R;
                    p2[0] = dS; p2[1] = dI; p2[2] = dR;
                }
            }
            // publish this chunk's I values for helpers
            if (lane < 2) {
                float* ihh = ih[h] + base;
#pragma unroll
                for (int j = 0; j < 32; ++j) ihh[j] = Iv[j];
            }
        } else {
            // far for chunk c+1 over t < 32c  (float4 data x float4 taps)
            const int A    = 32 + ((c + 1) << 5) + lane;  // rkp idx for t=0
            const int r    = (A + 1) & 3;                 // (A-3)%4, lane-fixed
            const int idx0 = (A - 3 - r) >> 2;
            const float4* tp  = (const float4*)rks4[r];
            const float4* ih4 = (const float4*)ih[fh];

            float h0 = 0.0f, h1 = 0.0f, h2 = 0.0f, h3 = 0.0f;
            const int nqb = 2 * c;                        // 4-float4 blocks
            for (int qb = half; qb < nqb; qb += 2) {
#pragma unroll
                for (int k = 0; k < 4; ++k) {
                    const int g = qb * 4 + k;
                    const float4 iv = ih4[g];
                    const float4 tv = tp[idx0 - g];       // rkp[A-4g-3 .. A-4g]
                    h0 = fmaf(tv.w, iv.x, h0);
                    h1 = fmaf(tv.z, iv.y, h1);
                    h2 = fmaf(tv.y, iv.z, h2);
                    h3 = fmaf(tv.x, iv.w, h3);
                }
            }
            const float res = (h0 + h1) + (h2 + h3);
            if (half == 0) fbA[(c + 1) & 1][lane][fh] = res;
            else           fbB[(c + 1) & 1][lane][fh] = res;
        }
        __syncthreads();
    }

    // ------------------- tail chunk c=31: 31 steps --------------------------
    {
        const int base = 31 << 5;   // 992
        if (w >= 1 && half == 0) {
            float cu = 0.0f;
            const float* ihh = ih[fh] + base - 32;
#pragma unroll
            for (int j = 0; j < 32; ++j)
                cu = fmaf(rkp[64 + lane - j], ihh[j], cu);
            fsum[lane][fh] = fbA[1][lane][fh] + fbB[1][lane][fh] + cu;
        }
        __syncthreads();

        if (w == 0) {
            float fr[4];
            fr[0] = fsum[0][h]; fr[1] = fsum[1][h];
            fr[2] = fsum[2][h]; fr[3] = fsum[3][h];

#pragma unroll
            for (int s = 0; s < 31; ++s) {
                Iv[s] = I;
                float a0 = fr[s & 3], a1 = 0.0f;
#pragma unroll
                for (int u = 0; u <= s; ++u) {
                    if (u & 1) a1 = fmaf(tapc[s - u], Iv[u], a1);
                    else       a0 = fmaf(tapc[s - u], Iv[u], a0);
                }
                if (s + 4 < 32) fr[(s + 4) & 3] = fsum[s + 4][h];

                const float integ = dt * (a0 + a1);
                const float bSI = beta * S * I;
                const float gI  = gamma * I;
                const float dS  = integ - bSI;
                const float dI  = bSI - gI;
                const float dR  = gI - integ;
                S = fmaf(dS, dt, S);
                I = fmaf(dI, dt, I);
                R = fmaf(dR, dt, R);

                if (lane < 2) {
                    float* p1 = ps_base + (base + s + 1) * OSTRIDE;
                    float* p2 = pd_base + (base + s) * OSTRIDE;
                    p1[0] = S;  p1[1] = I;  p1[2] = R;
                    p2[0] = dS; p2[1] = dI; p2[2] = dR;
                }
            }
        }
    }
}

// ---------------------------------------------------------------------------
// Launch: two kernels, stream-ordered, graph-capturable, allocation-free.
// Input order (metadata): t, y, w1, b1, w2, b2, w3, b3, w4, b4, beta, gamma
// Output: [solution (T,B,3) | diff (T,B,3)] float32
// ---------------------------------------------------------------------------
extern "C" void kernel_launch(void* const* d_in, const int* in_sizes, int n_in,
                              void* d_out, int out_size)
{
    const float* t  = (const float*)d_in[0];
    const float* y  = (const float*)d_in[1];
    const float* w1 = (const float*)d_in[2];
    const float* b1 = (const float*)d_in[3];
    const float* w2 = (const float*)d_in[4];
    const float* b2 = (const float*)d_in[5];
    const float* w3 = (const float*)d_in[6];
    const float* b3 = (const float*)d_in[7];
    const float* w4 = (const float*)d_in[8];
    const float* b4 = (const float*)d_in[9];
    const float* be = (const float*)d_in[10];
    const float* ga = (const float*)d_in[11];
    float* out = (float*)d_out;

    mlp_kernel<<<4, 256>>>(t, w1, b1, w2, b2, w3, b3, w4, b4);
    solver_kernel<<<B / 2, 160>>>(t, y, be, ga, out);
}

// round 12
// speedup vs baseline: 2.2988x; 1.0597x over previous
#include <cuda_runtime.h>
#include <math.h>

// Problem constants (fixed by the reference)
#define T  1024
#define B  256
#define H  20
#define OSTRIDE (B * 3)          // 768 floats between consecutive time rows
#define IHP 1060                 // ih row pitch (words): 16B-aligned, %32==4

// Memory kernel me[t] = sigmoid(MLP(t))
__device__ float g_me[T];

// ---------------------------------------------------------------------------
// Kernel 1: tiny MLP over the T time points. One thread per time point.
// ---------------------------------------------------------------------------
__global__ void mlp_kernel(const float* __restrict__ t,
                           const float* __restrict__ w1, const float* __restrict__ b1,
                           const float* __restrict__ w2, const float* __restrict__ b2,
                           const float* __restrict__ w3, const float* __restrict__ b3,
                           const float* __restrict__ w4, const float* __restrict__ b4)
{
    int i = blockIdx.x * blockDim.x + threadIdx.x;
    if (i >= T) return;
    float x = t[i];

    float h1[H], h2[H], h3[H];
#pragma unroll
    for (int j = 0; j < H; ++j) h1[j] = tanhf(x * w1[j] + b1[j]);

#pragma unroll
    for (int j = 0; j < H; ++j) {
        float s = b2[j];
#pragma unroll
        for (int k = 0; k < H; ++k) s += h1[k] * w2[k * H + j];
        h2[j] = tanhf(s);
    }

#pragma unroll
    for (int j = 0; j < H; ++j) {
        float s = b3[j];
#pragma unroll
        for (int k = 0; k < H; ++k) s += h2[k] * w3[k * H + j];
        h3[j] = tanhf(s);
    }

    float s = b4[0];
#pragma unroll
    for (int k = 0; k < H; ++k) s += h3[k] * w4[k];

    g_me[i] = 1.0f / (1.0f + expf(-s));   // sigmoid
}

// ---------------------------------------------------------------------------
// Kernel 2: BATCH-PER-LANE. 2 batches per block, 128 blocks (one wave).
//   warp 0      : state warp. Lane owns one batch (lane&1 -> batch; others
//                 mirror). Near sum = registers only. ZERO cross-lane ops.
//                 Outputs: ONE predicated scatter STG per step (lanes 0-11:
//                 sub=lane>>1 chooses S/I/R/dS/dI/dR, lane&1 chooses batch).
//                 History: ONE 2-address broadcast STS per step.
//   warps 1..4  : (h,half)=((w-1)>>1,(w-1)&1): far dot for chunk c+1 over
//                 t < 32c, float4 data + float4 taps (4 shifted rk copies).
//                 half==0 warps also do per-chunk catch-up + fsum fold.
// Per chunk: [phaseA: catchup+fsum] bar [phaseB: near | far(c+1)] bar.
// integ(idx=32c+s) = dt*( fsum[s] + sum_{u<=s} rk[s-u]*Iv[u] ).
// ---------------------------------------------------------------------------
__global__ void __launch_bounds__(160, 1)
solver_kernel(const float* __restrict__ t,
              const float* __restrict__ y,
              const float* __restrict__ beta_p,
              const float* __restrict__ gamma_p,
              float* __restrict__ out)
{
    __shared__ __align__(16) float rkp[1056];        // rkp[32+l]=rk[l]; [0..31]=0
    __shared__ __align__(16) float rks4[4][1088];    // rks4[r][i] = rkp[i+r] (0-pad)
    __shared__ __align__(16) float ih[2][IHP];       // per-batch I history
    __shared__ float fbA[2][32][2], fbB[2][32][2];   // far partials [parity][s][b]
    __shared__ float fsum[32][2];                    // far+catchup, per chunk

    const int tid  = threadIdx.x;
    const int w    = tid >> 5;
    const int lane = tid & 31;

    // ---- cooperative init ----
    for (int i = tid; i < 1056; i += 160)
        rkp[i] = (i < 32) ? 0.0f : g_me[T - 1 - (i - 32)];
    for (int i = tid; i < 4 * 1088; i += 160) {
        const int r = i / 1088, j = i - r * 1088, k = j + r;
        (&rks4[0][0])[i] = (k >= 32 && k < 1056) ? g_me[T - 1 - (k - 32)] : 0.0f;
    }
    for (int i = tid; i < 2 * IHP; i += 160) (&ih[0][0])[i] = 0.0f;
    if (tid < 128) { (&fbA[0][0][0])[tid] = 0.0f; (&fbB[0][0][0])[tid] = 0.0f; }

    const float dt    = t[0] - t[1];       // = 1/(T-1), positive
    const float beta  = beta_p[0];
    const float gamma = gamma_p[0];

    const int h  = lane & 1;               // lane's batch slot
    const int bb = blockIdx.x * 2 + h;     // global batch id

    float S = y[bb * 3 + 0];
    float I = y[bb * 3 + 1];
    float R = y[bb * 3 + 2];

    // Per-lane scatter-store mapping (state warp, lanes 0..11)
    const int  sub   = lane >> 1;          // 0..15 ; 0..5 are active
    const bool doSt  = (lane < 12);
    const bool isSol = (sub < 3);
    const int  comp  = isSol ? sub : sub - 3;       // 0..2
    const bool c0 = (comp == 0), c1 = (comp == 1);
    // solution row for step idx is idx+1 (fold +OSTRIDE); diff row is idx.
    float* stbase = isSol ? (out + bb * 3 + comp + OSTRIDE)
                          : (out + (size_t)T * OSTRIDE + bb * 3 + comp);

    if (w == 0 && lane < 2) {
        // solution[0] = y0 ; diff[T-1] = 0 (d_out poisoned -> must be written)
        float* p1 = out + bb * 3;
        p1[0] = S; p1[1] = I; p1[2] = R;
        float* pz = out + (size_t)T * OSTRIDE + (T - 1) * OSTRIDE + bb * 3;
        pz[0] = 0.0f; pz[1] = 0.0f; pz[2] = 0.0f;
    }
    __syncthreads();

    // State warp: scalar taps in registers (uniform across lanes).
    float tapc[32];
#pragma unroll
    for (int j = 0; j < 32; ++j) tapc[j] = rkp[32 + j];   // rk[j]

    const int fh   = (w >= 1) ? ((w - 1) >> 1) : 0;       // helper batch slot
    const int half = (w >= 1) ? ((w - 1) & 1) : 0;

    float* ihb = ih[h];                    // per-lane history row (2 addrs/warp)
    float Iv[32];

    // ------------------- chunks 0..30 (32 steps each) -----------------------
    for (int c = 0; c < 31; ++c) {
        const int base = c << 5;

        // phase A: catchup + fold into fsum (half==0 helper warps; lane = s)
        if (w >= 1 && half == 0) {
            float cu = 0.0f;
            if (c > 0) {
                const float* ihh = ih[fh] + base - 32;
#pragma unroll
                for (int j = 0; j < 32; ++j)
                    cu = fmaf(rkp[64 + lane - j], ihh[j], cu);   // rk[s+32-j]
            }
            fsum[lane][fh] = fbA[c & 1][lane][fh] + fbB[c & 1][lane][fh] + cu;
        }
        __syncthreads();

        // phase B
        if (w == 0) {
            // prefetch ring of fsum
            float fr[4];
            fr[0] = fsum[0][h]; fr[1] = fsum[1][h];
            fr[2] = fsum[2][h]; fr[3] = fsum[3][h];

            float* stc = stbase + base * OSTRIDE;

#pragma unroll
            for (int s = 0; s < 32; ++s) {
                Iv[s] = I;
                ihb[base + s] = I;          // all lanes; 2 distinct addrs/warp

                float a0 = fr[s & 3], a1 = 0.0f, a2 = 0.0f, a3 = 0.0f;
#pragma unroll
                for (int u = 0; u <= s; ++u) {
                    const float p = tapc[s - u];
                    if      ((u & 3) == 0) a0 = fmaf(p, Iv[u], a0);
                    else if ((u & 3) == 1) a1 = fmaf(p, Iv[u], a1);
                    else if ((u & 3) == 2) a2 = fmaf(p, Iv[u], a2);
                    else                   a3 = fmaf(p, Iv[u], a3);
                }
                if (s + 4 < 32) fr[(s + 4) & 3] = fsum[s + 4][h];

                const float integ = dt * ((a0 + a1) + (a2 + a3));
                const float bSI = beta * S * I;
                const float gI  = gamma * I;
                const float dS  = integ - bSI;
                const float dI  = bSI - gI;
                const float dR  = gI - integ;
                S = fmaf(dS, dt, S);
                I = fmaf(dI, dt, I);
                R = fmaf(dR, dt, R);

                // ONE predicated scatter store: 12 lanes, 1 STG instruction.
                const float vs = c0 ? S  : (c1 ? I  : R);
                const float vd = c0 ? dS : (c1 ? dI : dR);
                const float v  = isSol ? vs : vd;
                if (doSt) stc[s * OSTRIDE] = v;
            }
        } else {
            // far for chunk c+1 over t < 32c  (float4 data x float4 taps)
            const int A    = 32 + ((c + 1) << 5) + lane;  // rkp idx for t=0
            const int r    = (A + 1) & 3;                 // (A-3)%4, lane-fixed
            const int idx0 = (A - 3 - r) >> 2;
            const float4* tp  = (const float4*)rks4[r];
            const float4* ih4 = (const float4*)ih[fh];

            float h0 = 0.0f, h1 = 0.0f, h2 = 0.0f, h3 = 0.0f;
            const int nqb = 2 * c;                        // 4-float4 blocks
            for (int qb = half; qb < nqb; qb += 2) {
#pragma unroll
                for (int k = 0; k < 4; ++k) {
                    const int g = qb * 4 + k;
                    const float4 iv = ih4[g];
                    const float4 tv = tp[idx0 - g];       // rkp[A-4g-3 .. A-4g]
                    h0 = fmaf(tv.w, iv.x, h0);
                    h1 = fmaf(tv.z, iv.y, h1);
                    h2 = fmaf(tv.y, iv.z, h2);
                    h3 = fmaf(tv.x, iv.w, h3);
                }
            }
            const float res = (h0 + h1) + (h2 + h3);
            if (half == 0) fbA[(c + 1) & 1][lane][fh] = res;
            else           fbB[(c + 1) & 1][lane][fh] = res;
        }
        __syncthreads();
    }

    // ------------------- tail chunk c=31: 31 steps --------------------------
    {
        const int base = 31 << 5;   // 992
        if (w >= 1 && half == 0) {
            float cu = 0.0f;
            const float* ihh = ih[fh] + base - 32;
#pragma unroll
            for (int j = 0; j < 32; ++j)
                cu = fmaf(rkp[64 + lane - j], ihh[j], cu);
            fsum[lane][fh] = fbA[1][lane][fh] + fbB[1][lane][fh] + cu;
        }
        __syncthreads();

        if (w == 0) {
            float fr[4];
            fr[0] = fsum[0][h]; fr[1] = fsum[1][h];
            fr[2] = fsum[2][h]; fr[3] = fsum[3][h];

            float* stc = stbase + base * OSTRIDE;

#pragma unroll
            for (int s = 0; s < 31; ++s) {
                Iv[s] = I;
                float a0 = fr[s & 3], a1 = 0.0f, a2 = 0.0f, a3 = 0.0f;
#pragma unroll
                for (int u = 0; u <= s; ++u) {
                    const float p = tapc[s - u];
                    if      ((u & 3) == 0) a0 = fmaf(p, Iv[u], a0);
                    else if ((u & 3) == 1) a1 = fmaf(p, Iv[u], a1);
                    else if ((u & 3) == 2) a2 = fmaf(p, Iv[u], a2);
                    else                   a3 = fmaf(p, Iv[u], a3);
                }
                if (s + 4 < 32) fr[(s + 4) & 3] = fsum[s + 4][h];

                const float integ = dt * ((a0 + a1) + (a2 + a3));
                const float bSI = beta * S * I;
                const float gI  = gamma * I;
                const float dS  = integ - bSI;
                const float dI  = bSI - gI;
                const float dR  = gI - integ;
                S = fmaf(dS, dt, S);
                I = fmaf(dI, dt, I);
                R = fmaf(dR, dt, R);

                const float vs = c0 ? S  : (c1 ? I  : R);
                const float vd = c0 ? dS : (c1 ? dI : dR);
                const float v  = isSol ? vs : vd;
                if (doSt) stc[s * OSTRIDE] = v;
            }
        }
    }
}

// ---------------------------------------------------------------------------
// Launch: two kernels, stream-ordered, graph-capturable, allocation-free.
// Input order (metadata): t, y, w1, b1, w2, b2, w3, b3, w4, b4, beta, gamma
// Output: [solution (T,B,3) | diff (T,B,3)] float32
// ---------------------------------------------------------------------------
extern "C" void kernel_launch(void* const* d_in, const int* in_sizes, int n_in,
                              void* d_out, int out_size)
{
    const float* t  = (const float*)d_in[0];
    const float* y  = (const float*)d_in[1];
    const float* w1 = (const float*)d_in[2];
    const float* b1 = (const float*)d_in[3];
    const float* w2 = (const float*)d_in[4];
    const float* b2 = (const float*)d_in[5];
    const float* w3 = (const float*)d_in[6];
    const float* b3 = (const float*)d_in[7];
    const float* w4 = (const float*)d_in[8];
    const float* b4 = (const float*)d_in[9];
    const float* be = (const float*)d_in[10];
    const float* ga = (const float*)d_in[11];
    float* out = (float*)d_out;

    mlp_kernel<<<4, 256>>>(t, w1, b1, w2, b2, w3, b3, w4, b4);
    solver_kernel<<<B / 2, 160>>>(t, y, be, ga, out);
}

// round 13
// speedup vs baseline: 2.2995x; 1.0003x over previous
#include <cuda_runtime.h>
#include <math.h>

// Problem constants (fixed by the reference)
#define T  1024
#define B  256
#define H  20
#define OSTRIDE (B * 3)          // 768 floats between consecutive time rows
#define IHP 1060                 // ih row pitch (words): 16B-aligned, %32==4

// Memory kernel me[t] = sigmoid(MLP(t))
__device__ float g_me[T];

// ---------------------------------------------------------------------------
// Kernel 1: tiny MLP over the T time points. One thread per time point.
// ---------------------------------------------------------------------------
__global__ void mlp_kernel(const float* __restrict__ t,
                           const float* __restrict__ w1, const float* __restrict__ b1,
                           const float* __restrict__ w2, const float* __restrict__ b2,
                           const float* __restrict__ w3, const float* __restrict__ b3,
                           const float* __restrict__ w4, const float* __restrict__ b4)
{
    int i = blockIdx.x * blockDim.x + threadIdx.x;
    if (i >= T) return;
    float x = t[i];

    float h1[H], h2[H], h3[H];
#pragma unroll
    for (int j = 0; j < H; ++j) h1[j] = tanhf(x * w1[j] + b1[j]);

#pragma unroll
    for (int j = 0; j < H; ++j) {
        float s = b2[j];
#pragma unroll
        for (int k = 0; k < H; ++k) s += h1[k] * w2[k * H + j];
        h2[j] = tanhf(s);
    }

#pragma unroll
    for (int j = 0; j < H; ++j) {
        float s = b3[j];
#pragma unroll
        for (int k = 0; k < H; ++k) s += h2[k] * w3[k * H + j];
        h3[j] = tanhf(s);
    }

    float s = b4[0];
#pragma unroll
    for (int k = 0; k < H; ++k) s += h3[k] * w4[k];

    g_me[i] = 1.0f / (1.0f + expf(-s));   // sigmoid
}

// ---------------------------------------------------------------------------
// Kernel 2: BATCH-PER-LANE + output-reconstruction warp.
// 2 batches per block, 128 blocks (one wave). 6 warps:
//   w0         : state warp (lane&1 -> batch). Near triangle in registers,
//                publishes {S,I,dS,dI} per step as ONE STS.128 into a 3-slot
//                pub ring; no STG, no R/dR computation.
//   w1,w2,w3,w5: far warps (v=0..3). MERGED-batch far dot for chunk c+1:
//                one tap load feeds both batches' FMAs (halves tap traffic).
//                Phase A: w1/w2 do the 32-tap catch-up + fsum fold.
//   w4         : output warp (shares SMSP with w0; light). Lags 2 chunks:
//                reconstructs R = tot - S - I, dR = -(dS+dI) and does all
//                SEL+STG work (same scatter-store pattern as R12).
// ---------------------------------------------------------------------------
__global__ void __launch_bounds__(192, 1)
solver_kernel(const float* __restrict__ t,
              const float* __restrict__ y,
              const float* __restrict__ beta_p,
              const float* __restrict__ gamma_p,
              float* __restrict__ out)
{
    __shared__ __align__(16) float rkp[1056];        // rkp[32+l]=rk[l]; [0..31]=0
    __shared__ __align__(16) float rks4[4][1088];    // rks4[r][i] = rkp[i+r] (0-pad)
    __shared__ __align__(16) float ih[2][IHP];       // per-batch I history
    __shared__ float fb[4][2][32][2];                // far partials [v][parity][s][b]
    __shared__ float fsum[32][2];                    // far+catchup, per chunk
    __shared__ __align__(16) float pub[2][3][32][4]; // {S,I,dS,dI} ring [b][slot][s]

    const int tid  = threadIdx.x;
    const int w    = tid >> 5;
    const int lane = tid & 31;

    // ---- cooperative init ----
    for (int i = tid; i < 1056; i += 192)
        rkp[i] = (i < 32) ? 0.0f : g_me[T - 1 - (i - 32)];
    for (int i = tid; i < 4 * 1088; i += 192) {
        const int r = i / 1088, j = i - r * 1088, k = j + r;
        (&rks4[0][0])[i] = (k >= 32 && k < 1056) ? g_me[T - 1 - (k - 32)] : 0.0f;
    }
    for (int i = tid; i < 2 * IHP; i += 192) (&ih[0][0])[i] = 0.0f;
    for (int i = tid; i < 512; i += 192) (&fb[0][0][0][0])[i] = 0.0f;

    const float dt    = t[0] - t[1];       // = 1/(T-1), positive
    const float beta  = beta_p[0];
    const float gamma = gamma_p[0];

    const int h  = lane & 1;               // lane's batch slot
    const int bb = blockIdx.x * 2 + h;     // global batch id

    float S = y[bb * 3 + 0];
    float I = y[bb * 3 + 1];
    float R = y[bb * 3 + 2];
    const float tot = S + I + R;           // conserved: dS+dI+dR == 0

    // Output-warp per-lane scatter mapping (lanes 0..11): sub=lane>>1 picks
    // S/I/R/dS/dI/dR, lane&1 picks batch. Solution row for step idx is idx+1
    // (folded +OSTRIDE); diff row is idx.
    const int  sub   = lane >> 1;
    const bool doSt  = (lane < 12);
    const bool isSol = (sub < 3);
    const int  comp  = isSol ? sub : sub - 3;
    const bool cc0 = (comp == 0), cc1 = (comp == 1);
    float* stbase = isSol ? (out + bb * 3 + comp + OSTRIDE)
                          : (out + (size_t)T * OSTRIDE + bb * 3 + comp);

    if (w == 0 && lane < 2) {
        // solution[0] = y0 ; diff[T-1] = 0 (d_out poisoned -> must be written)
        float* p1 = out + bb * 3;
        p1[0] = S; p1[1] = I; p1[2] = R;
        float* pz = out + (size_t)T * OSTRIDE + (T - 1) * OSTRIDE + bb * 3;
        pz[0] = 0.0f; pz[1] = 0.0f; pz[2] = 0.0f;
    }
    if (w == 0 && lane == 0) ih[0][0] = 0.0f;  // overwritten below anyway
    __syncthreads();

    // State-warp taps (uniform scalars across lanes).
    float tapc[32];
#pragma unroll
    for (int j = 0; j < 32; ++j) tapc[j] = rkp[32 + j];   // rk[j]

    const int v = (w == 5) ? 3 : (w - 1);  // far-warp slice id (w in {1,2,3,5})

    float* ihb = ih[h];
    float Iv[32];

    // ------------------- chunks 0..30 (32 steps each) -----------------------
    for (int c = 0; c < 31; ++c) {
        const int base = c << 5;
        const int sl   = c % 3;            // pub write slot (off hot path)

        // phase A: catchup + fsum fold (w1 -> batch0, w2 -> batch1; lane = s)
        if (w == 1 || w == 2) {
            const int bA = w - 1;
            float cu = 0.0f;
            if (c > 0) {
                const float* ihh = ih[bA] + base - 32;
#pragma unroll
                for (int j = 0; j < 32; ++j)
                    cu = fmaf(rkp[64 + lane - j], ihh[j], cu);   // rk[s+32-j]
            }
            const int par = c & 1;
            fsum[lane][bA] = ((fb[0][par][lane][bA] + fb[1][par][lane][bA])
                            + (fb[2][par][lane][bA] + fb[3][par][lane][bA])) + cu;
        }
        __syncthreads();

        // phase B
        if (w == 0) {
            // ---- state warp: near chain ----
            float fr[4];
            fr[0] = fsum[0][h]; fr[1] = fsum[1][h];
            fr[2] = fsum[2][h]; fr[3] = fsum[3][h];

            float4* pubp = (float4*)&pub[h][sl][0][0];

#pragma unroll
            for (int s = 0; s < 32; ++s) {
                Iv[s] = I;
                ihb[base + s] = I;          // all lanes; 2 distinct addrs/warp

                float a0 = fr[s & 3], a1 = 0.0f, a2 = 0.0f, a3 = 0.0f;
#pragma unroll
                for (int u = 0; u <= s; ++u) {
                    const float p = tapc[s - u];
                    if      ((u & 3) == 0) a0 = fmaf(p, Iv[u], a0);
                    else if ((u & 3) == 1) a1 = fmaf(p, Iv[u], a1);
                    else if ((u & 3) == 2) a2 = fmaf(p, Iv[u], a2);
                    else                   a3 = fmaf(p, Iv[u], a3);
                }
                if (s + 4 < 32) fr[(s + 4) & 3] = fsum[s + 4][h];

                const float integ = dt * ((a0 + a1) + (a2 + a3));
                const float bSI = beta * S * I;
                const float gI  = gamma * I;
                const float dS  = integ - bSI;
                const float dI  = bSI - gI;
                S = fmaf(dS, dt, S);
                I = fmaf(dI, dt, I);

                pubp[s] = make_float4(S, I, dS, dI);   // 1 STS.128, 2 addrs/warp
            }
        } else if (w == 4) {
            // ---- output warp: flush chunk c-2 from the pub ring ----
            if (c >= 2) {
                const int co  = c - 2;
                const int slo = co % 3;
                const float4* pv4 = (const float4*)&pub[h][slo][0][0];
                float* stc = stbase + (co << 5) * OSTRIDE;
#pragma unroll 4
                for (int s = 0; s < 32; ++s) {
                    const float4 pv = pv4[s];
                    const float Rp = tot - pv.x - pv.y;
                    const float dR = -(pv.z + pv.w);
                    const float vs = cc0 ? pv.x : (cc1 ? pv.y : Rp);
                    const float vd = cc0 ? pv.z : (cc1 ? pv.w : dR);
                    const float vv = isSol ? vs : vd;
                    if (doSt) stc[s * OSTRIDE] = vv;
                }
            }
        } else {
            // ---- far warps (w1,w2,w3,w5): chunk c+1 over t < 32c, MERGED ----
            const int A    = 32 + ((c + 1) << 5) + lane;  // rkp idx for t=0
            const int r    = (A + 1) & 3;
            const int idx0 = (A - 3 - r) >> 2;
            const float4* tp  = (const float4*)rks4[r];
            const float4* i40 = (const float4*)ih[0];
            const float4* i41 = (const float4*)ih[1];

            float p00 = 0.0f, p01 = 0.0f, p02 = 0.0f, p03 = 0.0f;
            float p10 = 0.0f, p11 = 0.0f, p12 = 0.0f, p13 = 0.0f;
            const int ng = c << 3;                        // 8c float4 groups
#pragma unroll 4
            for (int g = v; g < ng; g += 4) {
                const float4 tv = tp[idx0 - g];           // rkp[A-4g-3 .. A-4g]
                const float4 a0 = i40[g];
                const float4 a1 = i41[g];
                p00 = fmaf(tv.w, a0.x, p00);
                p01 = fmaf(tv.z, a0.y, p01);
                p02 = fmaf(tv.y, a0.z, p02);
                p03 = fmaf(tv.x, a0.w, p03);
                p10 = fmaf(tv.w, a1.x, p10);
                p11 = fmaf(tv.z, a1.y, p11);
                p12 = fmaf(tv.y, a1.z, p12);
                p13 = fmaf(tv.x, a1.w, p13);
            }
            const int pnx = (c + 1) & 1;
            fb[v][pnx][lane][0] = (p00 + p01) + (p02 + p03);
            fb[v][pnx][lane][1] = (p10 + p11) + (p12 + p13);
        }
        __syncthreads();
    }

    // ------------------- tail chunk c=31: 31 steps --------------------------
    {
        const int base = 31 << 5;   // 992
        if (w == 1 || w == 2) {
            const int bA = w - 1;
            float cu = 0.0f;
            const float* ihh = ih[bA] + base - 32;
#pragma unroll
            for (int j = 0; j < 32; ++j)
                cu = fmaf(rkp[64 + lane - j], ihh[j], cu);
            fsum[lane][bA] = ((fb[0][1][lane][bA] + fb[1][1][lane][bA])
                            + (fb[2][1][lane][bA] + fb[3][1][lane][bA])) + cu;
        }
        __syncthreads();

        if (w == 0) {
            float fr[4];
            fr[0] = fsum[0][h]; fr[1] = fsum[1][h];
            fr[2] = fsum[2][h]; fr[3] = fsum[3][h];

            float4* pubp = (float4*)&pub[h][31 % 3][0][0];   // slot 1

#pragma unroll
            for (int s = 0; s < 31; ++s) {
                Iv[s] = I;
                float a0 = fr[s & 3], a1 = 0.0f, a2 = 0.0f, a3 = 0.0f;
#pragma unroll
                for (int u = 0; u <= s; ++u) {
                    const float p = tapc[s - u];
                    if      ((u & 3) == 0) a0 = fmaf(p, Iv[u], a0);
                    else if ((u & 3) == 1) a1 = fmaf(p, Iv[u], a1);
                    else if ((u & 3) == 2) a2 = fmaf(p, Iv[u], a2);
                    else                   a3 = fmaf(p, Iv[u], a3);
                }
                if (s + 4 < 32) fr[(s + 4) & 3] = fsum[s + 4][h];

                const float integ = dt * ((a0 + a1) + (a2 + a3));
                const float bSI = beta * S * I;
                const float gI  = gamma * I;
                const float dS  = integ - bSI;
                const float dI  = bSI - gI;
                S = fmaf(dS, dt, S);
                I = fmaf(dI, dt, I);

                pubp[s] = make_float4(S, I, dS, dI);
            }
        } else if (w == 4) {
            // flush chunk 29 (slot 29%3 = 2) during the tail
            const int co  = 29;
            const float4* pv4 = (const float4*)&pub[h][co % 3][0][0];
            float* stc = stbase + (co << 5) * OSTRIDE;
#pragma unroll 4
            for (int s = 0; s < 32; ++s) {
                const float4 pv = pv4[s];
                const float Rp = tot - pv.x - pv.y;
                const float dR = -(pv.z + pv.w);
                const float vs = cc0 ? pv.x : (cc1 ? pv.y : Rp);
                const float vd = cc0 ? pv.z : (cc1 ? pv.w : dR);
                const float vv = isSol ? vs : vd;
                if (doSt) stc[s * OSTRIDE] = vv;
            }
        }
        __syncthreads();
    }

    // ------------------- epilogue: flush chunks 30 and 31 -------------------
    if (w == 4) {
#pragma unroll
        for (int e = 0; e < 2; ++e) {
            const int co = 30 + e;
            const int ns = (e == 0) ? 32 : 31;
            const float4* pv4 = (const float4*)&pub[h][co % 3][0][0];
            float* stc = stbase + (co << 5) * OSTRIDE;
            for (int s = 0; s < ns; ++s) {
                const float4 pv = pv4[s];
                const float Rp = tot - pv.x - pv.y;
                const float dR = -(pv.z + pv.w);
                const float vs = cc0 ? pv.x : (cc1 ? pv.y : Rp);
                const float vd = cc0 ? pv.z : (cc1 ? pv.w : dR);
                const float vv = isSol ? vs : vd;
                if (doSt) stc[s * OSTRIDE] = vv;
            }
        }
    }
}

// ---------------------------------------------------------------------------
// Launch: two kernels, stream-ordered, graph-capturable, allocation-free.
// Input order (metadata): t, y, w1, b1, w2, b2, w3, b3, w4, b4, beta, gamma
// Output: [solution (T,B,3) | diff (T,B,3)] float32
// ---------------------------------------------------------------------------
extern "C" void kernel_launch(void* const* d_in, const int* in_sizes, int n_in,
                              void* d_out, int out_size)
{
    const float* t  = (const float*)d_in[0];
    const float* y  = (const float*)d_in[1];
    const float* w1 = (const float*)d_in[2];
    const float* b1 = (const float*)d_in[3];
    const float* w2 = (const float*)d_in[4];
    const float* b2 = (const float*)d_in[5];
    const float* w3 = (const float*)d_in[6];
    const float* b3 = (const float*)d_in[7];
    const float* w4 = (const float*)d_in[8];
    const float* b4 = (const float*)d_in[9];
    const float* be = (const float*)d_in[10];
    const float* ga = (const float*)d_in[11];
    float* out = (float*)d_out;

    mlp_kernel<<<4, 256>>>(t, w1, b1, w2, b2, w3, b3, w4, b4);
    solver_kernel<<<B / 2, 192>>>(t, y, be, ga, out);
}

// round 14
// speedup vs baseline: 2.9349x; 1.2763x over previous
#include <cuda_runtime.h>
#include <math.h>

// Problem constants (fixed by the reference)
#define T  1024
#define B  256
#define H  20
#define OSTRIDE (B * 3)          // 768 floats between consecutive time rows
#define IHP 1060                 // ih row pitch (words): 16B-aligned, %32==4

// Memory kernel me[t] = sigmoid(MLP(t))
__device__ float g_me[T];

// ---------------------------------------------------------------------------
// Kernel 1: tiny MLP over the T time points. One thread per time point.
// ---------------------------------------------------------------------------
__global__ void mlp_kernel(const float* __restrict__ t,
                           const float* __restrict__ w1, const float* __restrict__ b1,
                           const float* __restrict__ w2, const float* __restrict__ b2,
                           const float* __restrict__ w3, const float* __restrict__ b3,
                           const float* __restrict__ w4, const float* __restrict__ b4)
{
    int i = blockIdx.x * blockDim.x + threadIdx.x;
    if (i >= T) return;
    float x = t[i];

    float h1[H], h2[H], h3[H];
#pragma unroll
    for (int j = 0; j < H; ++j) h1[j] = tanhf(x * w1[j] + b1[j]);

#pragma unroll
    for (int j = 0; j < H; ++j) {
        float s = b2[j];
#pragma unroll
        for (int k = 0; k < H; ++k) s += h1[k] * w2[k * H + j];
        h2[j] = tanhf(s);
    }

#pragma unroll
    for (int j = 0; j < H; ++j) {
        float s = b3[j];
#pragma unroll
        for (int k = 0; k < H; ++k) s += h2[k] * w3[k * H + j];
        h3[j] = tanhf(s);
    }

    float s = b4[0];
#pragma unroll
    for (int k = 0; k < H; ++k) s += h3[k] * w4[k];

    g_me[i] = 1.0f / (1.0f + expf(-s));   // sigmoid
}

// ---------------------------------------------------------------------------
// Kernel 2: BATCH-PER-LANE, role-per-SMSP. 2 batches/block, 128 blocks.
// 5 warps (wid%4 -> SMSP):
//   w0 (S0): state+output. Near triangle in registers, R12 single scatter STG.
//   w4 (S0): catchup warp — computes fsum (far fold + 32-tap catch-up) for
//            BOTH batches at chunk start, then idles. Syncs with w0 via
//            named bar.sync 1,64 — far warps are NOT blocked by catchup.
//   w1/w2/w3 (S1/S2/S3): merged-batch far dot for chunk c+1 over t<32c
//            (one tap load feeds both batches' FMAs), stride 3.
// ONE full __syncthreads per chunk.
// integ(idx=32c+s) = dt*( fsumP[h][s] + sum_{u<=s} rk[s-u]*Iv[u] ).
// ---------------------------------------------------------------------------
__global__ void __launch_bounds__(160, 1)
solver_kernel(const float* __restrict__ t,
              const float* __restrict__ y,
              const float* __restrict__ beta_p,
              const float* __restrict__ gamma_p,
              float* __restrict__ out)
{
    __shared__ __align__(16) float rkp[1056];        // rkp[32+l]=rk[l]; [0..31]=0
    __shared__ __align__(16) float rks4[4][1088];    // rks4[r][i] = rkp[i+r] (0-pad)
    __shared__ __align__(16) float ih[2][IHP];       // per-batch I history
    __shared__ float fb[3][2][32][2];                // far partials [v][parity][s][b]
    __shared__ __align__(16) float fsumP[2][32];     // far+catchup, batch-major

    const int tid  = threadIdx.x;
    const int w    = tid >> 5;
    const int lane = tid & 31;

    // ---- cooperative init ----
    for (int i = tid; i < 1056; i += 160)
        rkp[i] = (i < 32) ? 0.0f : g_me[T - 1 - (i - 32)];
    for (int i = tid; i < 4 * 1088; i += 160) {
        const int r = i / 1088, j = i - r * 1088, k = j + r;
        (&rks4[0][0])[i] = (k >= 32 && k < 1056) ? g_me[T - 1 - (k - 32)] : 0.0f;
    }
    for (int i = tid; i < 2 * IHP; i += 160) (&ih[0][0])[i] = 0.0f;
    for (int i = tid; i < 384; i += 160) (&fb[0][0][0][0])[i] = 0.0f;

    const float dt    = t[0] - t[1];       // = 1/(T-1), positive
    const float beta  = beta_p[0];
    const float gamma = gamma_p[0];

    const int h  = lane & 1;               // lane's batch slot
    const int bb = blockIdx.x * 2 + h;     // global batch id

    float S = y[bb * 3 + 0];
    float I = y[bb * 3 + 1];
    float R = y[bb * 3 + 2];

    // w0 per-lane scatter-store mapping (lanes 0..11): sub=lane>>1 picks
    // S/I/R/dS/dI/dR, lane&1 picks batch. Solution row for step idx is idx+1
    // (folded +OSTRIDE); diff row is idx.
    const int  sub   = lane >> 1;
    const bool doSt  = (lane < 12);
    const bool isSol = (sub < 3);
    const int  comp  = isSol ? sub : sub - 3;
    const bool cc0 = (comp == 0), cc1 = (comp == 1);
    float* stbase = isSol ? (out + bb * 3 + comp + OSTRIDE)
                          : (out + (size_t)T * OSTRIDE + bb * 3 + comp);

    if (w == 0 && lane < 2) {
        // solution[0] = y0 ; diff[T-1] = 0 (d_out poisoned -> must be written)
        float* p1 = out + bb * 3;
        p1[0] = S; p1[1] = I; p1[2] = R;
        float* pz = out + (size_t)T * OSTRIDE + (T - 1) * OSTRIDE + bb * 3;
        pz[0] = 0.0f; pz[1] = 0.0f; pz[2] = 0.0f;
    }
    __syncthreads();

    // State-warp taps (uniform scalars across lanes).
    float tapc[32];
#pragma unroll
    for (int j = 0; j < 32; ++j) tapc[j] = rkp[32 + j];   // rk[j]

    float* ihb = ih[h];
    float Iv[32];

    // ------------------- chunks 0..30 (32 steps each) -----------------------
    for (int c = 0; c < 31; ++c) {
        const int base = c << 5;

        if (w == 4) {
            // ---- catchup warp: fsum for both batches (lane = s) ----
#pragma unroll
            for (int bA = 0; bA < 2; ++bA) {
                float c0 = 0.0f, c1 = 0.0f, c2 = 0.0f, c3 = 0.0f;
                if (c > 0) {
                    const float* ihh = ih[bA] + base - 32;
#pragma unroll
                    for (int j = 0; j < 32; j += 4) {
                        c0 = fmaf(rkp[64 + lane - j],     ihh[j],     c0);
                        c1 = fmaf(rkp[63 + lane - j],     ihh[j + 1], c1);
                        c2 = fmaf(rkp[62 + lane - j],     ihh[j + 2], c2);
                        c3 = fmaf(rkp[61 + lane - j],     ihh[j + 3], c3);
                    }
                }
                const int par = c & 1;
                fsumP[bA][lane] = ((fb[0][par][lane][bA] + fb[1][par][lane][bA])
                                   + fb[2][par][lane][bA]) + ((c0 + c1) + (c2 + c3));
            }
            asm volatile("bar.sync 1, 64;" ::: "memory");   // release w0
        } else if (w == 0) {
            asm volatile("bar.sync 1, 64;" ::: "memory");   // wait for fsum

            // ---- state warp: near chain ----
            const float4* p4 = (const float4*)fsumP[h];     // 2 addrs/warp
            float4 fq0 = p4[0], fq1;

            float* stc = stbase + base * OSTRIDE;

#pragma unroll
            for (int s = 0; s < 32; ++s) {
                // double-buffered fsum prefetch (all indices compile-time)
                if ((s & 3) == 0 && s + 4 < 32) {
                    if (((s >> 2) + 1) & 1) fq1 = p4[(s >> 2) + 1];
                    else                    fq0 = p4[(s >> 2) + 1];
                }
                const float4 fc = ((s >> 2) & 1) ? fq1 : fq0;
                const float  fs = ((s & 3) == 0) ? fc.x :
                                  ((s & 3) == 1) ? fc.y :
                                  ((s & 3) == 2) ? fc.z : fc.w;

                Iv[s] = I;
                ihb[base + s] = I;          // all lanes; 2 distinct addrs/warp

                float a0 = fs, a1 = 0.0f, a2 = 0.0f, a3 = 0.0f;
#pragma unroll
                for (int u = 0; u <= s; ++u) {
                    const float p = tapc[s - u];
                    if      ((u & 3) == 0) a0 = fmaf(p, Iv[u], a0);
                    else if ((u & 3) == 1) a1 = fmaf(p, Iv[u], a1);
                    else if ((u & 3) == 2) a2 = fmaf(p, Iv[u], a2);
                    else                   a3 = fmaf(p, Iv[u], a3);
                }

                const float integ = dt * ((a0 + a1) + (a2 + a3));
                const float bSI = beta * S * I;
                const float gI  = gamma * I;
                const float dS  = integ - bSI;
                const float dI  = bSI - gI;
                const float dR  = gI - integ;
                S = fmaf(dS, dt, S);
                I = fmaf(dI, dt, I);
                R = fmaf(dR, dt, R);

                // ONE predicated scatter store: 12 lanes, 1 STG instruction.
                const float vs = cc0 ? S  : (cc1 ? I  : R);
                const float vd = cc0 ? dS : (cc1 ? dI : dR);
                const float v  = isSol ? vs : vd;
                if (doSt) stc[s * OSTRIDE] = v;
            }
        } else {
            // ---- far warps w1..w3 (v=w-1): chunk c+1 over t < 32c, MERGED ----
            const int v    = w - 1;
            const int A    = 32 + ((c + 1) << 5) + lane;  // rkp idx for t=0
            const int r    = (A + 1) & 3;
            const int idx0 = (A - 3 - r) >> 2;
            const float4* tp  = (const float4*)rks4[r];
            const float4* i40 = (const float4*)ih[0];
            const float4* i41 = (const float4*)ih[1];

            float p00 = 0.0f, p01 = 0.0f, p02 = 0.0f, p03 = 0.0f;
            float p10 = 0.0f, p11 = 0.0f, p12 = 0.0f, p13 = 0.0f;
            const int ng = c << 3;                        // 8c float4 groups
#pragma unroll 4
            for (int g = v; g < ng; g += 3) {
                const float4 tv = tp[idx0 - g];           // rkp[A-4g-3 .. A-4g]
                const float4 a0 = i40[g];
                const float4 a1 = i41[g];
                p00 = fmaf(tv.w, a0.x, p00);
                p01 = fmaf(tv.z, a0.y, p01);
                p02 = fmaf(tv.y, a0.z, p02);
                p03 = fmaf(tv.x, a0.w, p03);
                p10 = fmaf(tv.w, a1.x, p10);
                p11 = fmaf(tv.z, a1.y, p11);
                p12 = fmaf(tv.y, a1.z, p12);
                p13 = fmaf(tv.x, a1.w, p13);
            }
            const int pnx = (c + 1) & 1;
            fb[v][pnx][lane][0] = (p00 + p01) + (p02 + p03);
            fb[v][pnx][lane][1] = (p10 + p11) + (p12 + p13);
        }
        __syncthreads();   // single full barrier per chunk
    }

    // ------------------- tail chunk c=31: 31 steps --------------------------
    {
        const int base = 31 << 5;   // 992
        if (w == 4) {
#pragma unroll
            for (int bA = 0; bA < 2; ++bA) {
                float c0 = 0.0f, c1 = 0.0f, c2 = 0.0f, c3 = 0.0f;
                const float* ihh = ih[bA] + base - 32;
#pragma unroll
                for (int j = 0; j < 32; j += 4) {
                    c0 = fmaf(rkp[64 + lane - j], ihh[j],     c0);
                    c1 = fmaf(rkp[63 + lane - j], ihh[j + 1], c1);
                    c2 = fmaf(rkp[62 + lane - j], ihh[j + 2], c2);
                    c3 = fmaf(rkp[61 + lane - j], ihh[j + 3], c3);
                }
                fsumP[bA][lane] = ((fb[0][1][lane][bA] + fb[1][1][lane][bA])
                                   + fb[2][1][lane][bA]) + ((c0 + c1) + (c2 + c3));
            }
            asm volatile("bar.sync 1, 64;" ::: "memory");
        } else if (w == 0) {
            asm volatile("bar.sync 1, 64;" ::: "memory");

            const float4* p4 = (const float4*)fsumP[h];
            float4 fq0 = p4[0], fq1;

            float* stc = stbase + base * OSTRIDE;

#pragma unroll
            for (int s = 0; s < 31; ++s) {
                if ((s & 3) == 0 && s + 4 < 32) {
                    if (((s >> 2) + 1) & 1) fq1 = p4[(s >> 2) + 1];
                    else                    fq0 = p4[(s >> 2) + 1];
                }
                const float4 fc = ((s >> 2) & 1) ? fq1 : fq0;
                const float  fs = ((s & 3) == 0) ? fc.x :
                                  ((s & 3) == 1) ? fc.y :
                                  ((s & 3) == 2) ? fc.z : fc.w;

                Iv[s] = I;
                float a0 = fs, a1 = 0.0f, a2 = 0.0f, a3 = 0.0f;
#pragma unroll
                for (int u = 0; u <= s; ++u) {
                    const float p = tapc[s - u];
                    if      ((u & 3) == 0) a0 = fmaf(p, Iv[u], a0);
                    else if ((u & 3) == 1) a1 = fmaf(p, Iv[u], a1);
                    else if ((u & 3) == 2) a2 = fmaf(p, Iv[u], a2);
                    else                   a3 = fmaf(p, Iv[u], a3);
                }

                const float integ = dt * ((a0 + a1) + (a2 + a3));
                const float bSI = beta * S * I;
                const float gI  = gamma * I;
                const float dS  = integ - bSI;
                const float dI  = bSI - gI;
                const float dR  = gI - integ;
                S = fmaf(dS, dt, S);
                I = fmaf(dI, dt, I);
                R = fmaf(dR, dt, R);

                const float vs = cc0 ? S  : (cc1 ? I  : R);
                const float vd = cc0 ? dS : (cc1 ? dI : dR);
                const float v  = isSol ? vs : vd;
                if (doSt) stc[s * OSTRIDE] = v;
            }
        }
        // far warps: nothing left; kernel ends (no trailing barrier needed)
    }
}

// ---------------------------------------------------------------------------
// Launch: two kernels, stream-ordered, graph-capturable, allocation-free.
// Input order (metadata): t, y, w1, b1, w2, b2, w3, b3, w4, b4, beta, gamma
// Output: [solution (T,B,3) | diff (T,B,3)] float32
// ---------------------------------------------------------------------------
extern "C" void kernel_launch(void* const* d_in, const int* in_sizes, int n_in,
                              void* d_out, int out_size)
{
    const float* t  = (const float*)d_in[0];
    const float* y  = (const float*)d_in[1];
    const float* w1 = (const float*)d_in[2];
    const float* b1 = (const float*)d_in[3];
    const float* w2 = (const float*)d_in[4];
    const float* b2 = (const float*)d_in[5];
    const float* w3 = (const float*)d_in[6];
    const float* b3 = (const float*)d_in[7];
    const float* w4 = (const float*)d_in[8];
    const float* b4 = (const float*)d_in[9];
    const float* be = (const float*)d_in[10];
    const float* ga = (const float*)d_in[11];
    float* out = (float*)d_out;

    mlp_kernel<<<4, 256>>>(t, w1, b1, w2, b2, w3, b3, w4, b4);
    solver_kernel<<<B / 2, 160>>>(t, y, be, ga, out);
}